// round 9
// baseline (speedup 1.0000x reference)
#include <cuda_runtime.h>
#include <cuda_fp16.h>
#include <cstdint>

// Problem constants (fixed by the reference)
#define BB 8
#define CC 128
#define HH 128
#define WW 128
#define PP 32768
#define HW (HH * WW)

// Scratch: feat_grid transposed to [B, H*W, C] channels-last, fp16. 33.5 MB.
__device__ __half g_featT[BB * HW * CC];

// bit-cast helpers
static __device__ __forceinline__ unsigned h2_to_u32(__half2 h) {
    return *reinterpret_cast<unsigned*>(&h);
}
static __device__ __forceinline__ __half2 u32_to_h2(unsigned u) {
    return *reinterpret_cast<__half2*>(&u);
}

// ---------------------------------------------------------------------------
// Kernel 1: per-batch tiled transpose + f32->fp16: src[C][HW] -> dstT[HW][C]
// Tile: 32 channels x 128 hw. grid: (HW/128, CC/32), block: (32, 8).
// ---------------------------------------------------------------------------
__global__ void transpose_kernel(const float* __restrict__ src, int b) {
    __shared__ float tile[32][129];

    const int hw0 = blockIdx.x * 128;
    const int c0 = blockIdx.y * 32;
    const float* sb = src + (size_t)b * CC * HW;
    __half2* db = (__half2*)(g_featT + (size_t)b * HW * CC);

    const int tx = threadIdx.x, ty = threadIdx.y;

    // read: each thread loads 4 float4 (rows c0+ty+8j, cols hw0+4tx..)
#pragma unroll
    for (int jj = 0; jj < 4; jj++) {
        const int c = ty + jj * 8;
        const float4 v = __ldcs((const float4*)&sb[(size_t)(c0 + c) * HW + hw0] + tx);
        tile[c][4 * tx + 0] = v.x;
        tile[c][4 * tx + 1] = v.y;
        tile[c][4 * tx + 2] = v.z;
        tile[c][4 * tx + 3] = v.w;
    }
    __syncthreads();

    // write: thread t -> h2 col (t&15), row group (t>>4); 8 passes of 16 rows
    const int t = ty * 32 + tx;
    const int col = t & 15;
    const int rowg = t >> 4;
#pragma unroll
    for (int pass = 0; pass < 8; pass++) {
        const int row = rowg + pass * 16;
        const float lo = tile[2 * col][row];
        const float hi = tile[2 * col + 1][row];
        db[(size_t)(hw0 + row) * (CC / 2) + (c0 >> 1) + col] =
            __floats2half2_rn(lo, hi);
    }
}

// ---------------------------------------------------------------------------
// Kernel 2: per-batch gather. EIGHT points per warp, all 32 lanes = unique
// (point, corner) slot. 32 independent LDG.64 corner reads, HFMA2 accum.
// ---------------------------------------------------------------------------
__global__ __launch_bounds__(256) void gather_kernel(
    const float* __restrict__ tk_codes,   // [B, P, 2]
    float* __restrict__ out,              // [B, P, C]
    int b)
{
    const unsigned FULL = 0xffffffffu;
    const int oct = (blockIdx.x * blockDim.x + threadIdx.x) >> 5;  // within batch
    const int lane = threadIdx.x & 31;

    const int p0 = b * PP + oct * 8;         // first (global) point of group
    const int j = lane >> 2;                 // this lane's point (0..7)
    const int k = lane & 3;                  // this lane's corner

    const float2 pt = __ldg(((const float2*)tk_codes) + p0 + j);
    const float x = pt.x;
    const float y = pt.y;

    const bool inb = (x >= 0.0f) & (y >= 0.0f) &
                     (x <= (float)(WW - 1)) & (y <= (float)(HH - 1));

    // corner order: (fx,fy),(fx,cy),(cx,fy),(cx,cy)
    const float cxk = (k & 2) ? ceilf(x) : floorf(x);
    const float cyk = (k & 1) ? ceilf(y) : floorf(y);

    int gx = ((int)cxk) % WW;   // C-style %: matches jnp.fmod on int32
    int gy = ((int)cyk) % HH;
    gx = max(gx, 0);
    gy = max(gy, 0);

    const float dx = x - (float)gx;
    const float dy = y - (float)gy;
    float w = inb ? __fdividef(1.0f, sqrtf(dx * dx + dy * dy) + 1e-10f) : 0.0f;

    float d = w + __shfl_xor_sync(FULL, w, 1);
    d += __shfl_xor_sync(FULL, d, 2);
    if (d == 0.0f) d = 1.0f;
    w *= __fdividef(1.0f, d);               // normalized weight in [0,1]

    const int idx = (gy << 7) + gx;
    const unsigned hw2 = h2_to_u32(__float2half2_rn(w));

    const uint2* __restrict__ baseT =
        (const uint2*)(g_featT + (size_t)b * HW * CC);
    float4* __restrict__ o4 = (float4*)out;

#pragma unroll
    for (int p = 0; p < 8; p++) {
        const int s = p * 4;
        const __half2 w0 = u32_to_h2(__shfl_sync(FULL, hw2, s + 0));
        const __half2 w1 = u32_to_h2(__shfl_sync(FULL, hw2, s + 1));
        const __half2 w2 = u32_to_h2(__shfl_sync(FULL, hw2, s + 2));
        const __half2 w3 = u32_to_h2(__shfl_sync(FULL, hw2, s + 3));
        const int i0 = __shfl_sync(FULL, idx, s + 0);
        const int i1 = __shfl_sync(FULL, idx, s + 1);
        const int i2 = __shfl_sync(FULL, idx, s + 2);
        const int i3 = __shfl_sync(FULL, idx, s + 3);

        const uint2 r0 = baseT[(size_t)i0 * 32 + lane];
        const uint2 r1 = baseT[(size_t)i1 * 32 + lane];
        const uint2 r2 = baseT[(size_t)i2 * 32 + lane];
        const uint2 r3 = baseT[(size_t)i3 * 32 + lane];

        __half2 a0 = __hmul2(w0, u32_to_h2(r0.x));
        __half2 a1 = __hmul2(w0, u32_to_h2(r0.y));
        a0 = __hfma2(w1, u32_to_h2(r1.x), a0);
        a1 = __hfma2(w1, u32_to_h2(r1.y), a1);
        a0 = __hfma2(w2, u32_to_h2(r2.x), a0);
        a1 = __hfma2(w2, u32_to_h2(r2.y), a1);
        a0 = __hfma2(w3, u32_to_h2(r3.x), a0);
        a1 = __hfma2(w3, u32_to_h2(r3.y), a1);

        const float2 f0 = __half22float2(a0);
        const float2 f1 = __half22float2(a1);
        __stcs(o4 + (size_t)(p0 + p) * 32 + lane,
               make_float4(f0.x, f0.y, f1.x, f1.y));
    }
}

// ---------------------------------------------------------------------------
// Launch: per-batch pipeline. Transposes run on a forked stream; gather(b)
// waits (via event edge) on transpose(b). Stream capture turns the event
// record/wait pairs into graph dependency edges — launches only, no syncs.
// ---------------------------------------------------------------------------
extern "C" void kernel_launch(void* const* d_in, const int* in_sizes, int n_in,
                              void* d_out, int out_size) {
    const float* tk_codes = (const float*)d_in[0];   // [B, P, 2] float32
    const float* feat     = (const float*)d_in[1];   // [B, C, H, W] float32
    float* out            = (float*)d_out;           // [B, P, C] float32

    (void)in_sizes; (void)n_in; (void)out_size;

    // lazily-created side stream + events (resources only; work is identical
    // on every call)
    static cudaStream_t s2 = nullptr;
    static cudaEvent_t evFork = nullptr;
    static cudaEvent_t evT[BB];
    if (s2 == nullptr) {
        cudaStreamCreateWithFlags(&s2, cudaStreamNonBlocking);
        cudaEventCreateWithFlags(&evFork, cudaEventDisableTiming);
        for (int b = 0; b < BB; b++)
            cudaEventCreateWithFlags(&evT[b], cudaEventDisableTiming);
    }

    dim3 tgrid(HW / 128, CC / 32);
    dim3 tblock(32, 8);
    const int gblocks = (PP / 8) * 32 / 256;     // 512 blocks per batch

    // fork s2 off the main (capture) stream
    cudaEventRecord(evFork, 0);
    cudaStreamWaitEvent(s2, evFork, 0);

    for (int b = 0; b < BB; b++) {
        transpose_kernel<<<tgrid, tblock, 0, s2>>>(feat, b);
        cudaEventRecord(evT[b], s2);
    }
    for (int b = 0; b < BB; b++) {
        cudaStreamWaitEvent(0, evT[b], 0);       // gather(b) needs featT[b]
        gather_kernel<<<gblocks, 256>>>(tk_codes, out, b);
    }
    // join: the last gather already waits on evT[BB-1] (tail of s2), so all
    // forked work is reachable from the capture stream's final node.
}

// round 10
// speedup vs baseline: 1.2588x; 1.2588x over previous
#include <cuda_runtime.h>
#include <cuda_fp16.h>
#include <cstdint>

// Problem constants (fixed by the reference)
#define BB 8
#define CC 128
#define HH 128
#define WW 128
#define PP 32768
#define HW (HH * WW)

#define HALFB (BB / 2)   // 4 batches per pipeline stage

// Scratch: feat_grid transposed to [B, H*W, C] channels-last, fp16. 33.5 MB.
__device__ __half g_featT[BB * HW * CC];

// bit-cast helpers
static __device__ __forceinline__ unsigned h2_to_u32(__half2 h) {
    return *reinterpret_cast<unsigned*>(&h);
}
static __device__ __forceinline__ __half2 u32_to_h2(unsigned u) {
    return *reinterpret_cast<__half2*>(&u);
}

// ---------------------------------------------------------------------------
// Kernel 1: tiled transpose + f32->fp16 for 4 batches [b0, b0+4):
// src[C][HW] -> dstT[HW][C].  grid: (HW/128, CC/32, 4), block: (32, 8).
// ---------------------------------------------------------------------------
__global__ void transpose_kernel(const float* __restrict__ src, int b0) {
    __shared__ float tile[32][129];

    const int b = b0 + blockIdx.z;
    const int hw0 = blockIdx.x * 128;
    const int c0 = blockIdx.y * 32;
    const float* sb = src + (size_t)b * CC * HW;
    __half2* db = (__half2*)(g_featT + (size_t)b * HW * CC);

    const int tx = threadIdx.x, ty = threadIdx.y;

    // read: each thread loads 4 float4 (rows c0+ty+8j, cols hw0+4tx..)
#pragma unroll
    for (int jj = 0; jj < 4; jj++) {
        const int c = ty + jj * 8;
        const float4 v = __ldcs((const float4*)&sb[(size_t)(c0 + c) * HW + hw0] + tx);
        tile[c][4 * tx + 0] = v.x;
        tile[c][4 * tx + 1] = v.y;
        tile[c][4 * tx + 2] = v.z;
        tile[c][4 * tx + 3] = v.w;
    }
    __syncthreads();

    // write: thread t -> h2 col (t&15), row group (t>>4); 8 passes of 16 rows
    const int t = ty * 32 + tx;
    const int col = t & 15;
    const int rowg = t >> 4;
#pragma unroll
    for (int pass = 0; pass < 8; pass++) {
        const int row = rowg + pass * 16;
        const float lo = tile[2 * col][row];
        const float hi = tile[2 * col + 1][row];
        db[(size_t)(hw0 + row) * (CC / 2) + (c0 >> 1) + col] =
            __floats2half2_rn(lo, hi);
    }
}

// ---------------------------------------------------------------------------
// Kernel 2: gather for 4 batches starting at b0. EIGHT points per warp, all
// 32 lanes = unique (point, corner) slot. 32 independent LDG.64 corner reads.
// ---------------------------------------------------------------------------
__global__ __launch_bounds__(256) void gather_kernel(
    const float* __restrict__ tk_codes,   // [B, P, 2]
    float* __restrict__ out,              // [B, P, C]
    int b0)
{
    const unsigned FULL = 0xffffffffu;
    const int oct = (blockIdx.x * blockDim.x + threadIdx.x) >> 5;
    const int lane = threadIdx.x & 31;

    const int p0 = b0 * PP + oct * 8;        // first (global) point of group
    const int j = lane >> 2;                 // this lane's point (0..7)
    const int k = lane & 3;                  // this lane's corner

    const float2 pt = __ldg(((const float2*)tk_codes) + p0 + j);
    const float x = pt.x;
    const float y = pt.y;

    const bool inb = (x >= 0.0f) & (y >= 0.0f) &
                     (x <= (float)(WW - 1)) & (y <= (float)(HH - 1));

    // corner order: (fx,fy),(fx,cy),(cx,fy),(cx,cy)
    const float cxk = (k & 2) ? ceilf(x) : floorf(x);
    const float cyk = (k & 1) ? ceilf(y) : floorf(y);

    int gx = ((int)cxk) % WW;   // C-style %: matches jnp.fmod on int32
    int gy = ((int)cyk) % HH;
    gx = max(gx, 0);
    gy = max(gy, 0);

    const float dx = x - (float)gx;
    const float dy = y - (float)gy;
    float w = inb ? __fdividef(1.0f, sqrtf(dx * dx + dy * dy) + 1e-10f) : 0.0f;

    float d = w + __shfl_xor_sync(FULL, w, 1);
    d += __shfl_xor_sync(FULL, d, 2);
    if (d == 0.0f) d = 1.0f;
    w *= __fdividef(1.0f, d);               // normalized weight in [0,1]

    const int idx = (gy << 7) + gx;
    const unsigned hw2 = h2_to_u32(__float2half2_rn(w));

    const int b = p0 >> 15;                  // P = 32768; group never spans batches
    const uint2* __restrict__ baseT =
        (const uint2*)(g_featT + (size_t)b * HW * CC);
    float4* __restrict__ o4 = (float4*)out;

#pragma unroll
    for (int p = 0; p < 8; p++) {
        const int s = p * 4;
        const __half2 w0 = u32_to_h2(__shfl_sync(FULL, hw2, s + 0));
        const __half2 w1 = u32_to_h2(__shfl_sync(FULL, hw2, s + 1));
        const __half2 w2 = u32_to_h2(__shfl_sync(FULL, hw2, s + 2));
        const __half2 w3 = u32_to_h2(__shfl_sync(FULL, hw2, s + 3));
        const int i0 = __shfl_sync(FULL, idx, s + 0);
        const int i1 = __shfl_sync(FULL, idx, s + 1);
        const int i2 = __shfl_sync(FULL, idx, s + 2);
        const int i3 = __shfl_sync(FULL, idx, s + 3);

        const uint2 r0 = baseT[(size_t)i0 * 32 + lane];
        const uint2 r1 = baseT[(size_t)i1 * 32 + lane];
        const uint2 r2 = baseT[(size_t)i2 * 32 + lane];
        const uint2 r3 = baseT[(size_t)i3 * 32 + lane];

        __half2 a0 = __hmul2(w0, u32_to_h2(r0.x));
        __half2 a1 = __hmul2(w0, u32_to_h2(r0.y));
        a0 = __hfma2(w1, u32_to_h2(r1.x), a0);
        a1 = __hfma2(w1, u32_to_h2(r1.y), a1);
        a0 = __hfma2(w2, u32_to_h2(r2.x), a0);
        a1 = __hfma2(w2, u32_to_h2(r2.y), a1);
        a0 = __hfma2(w3, u32_to_h2(r3.x), a0);
        a1 = __hfma2(w3, u32_to_h2(r3.y), a1);

        const float2 f0 = __half22float2(a0);
        const float2 f1 = __half22float2(a1);
        __stcs(o4 + (size_t)(p0 + p) * 32 + lane,
               make_float4(f0.x, f0.y, f1.x, f1.y));
    }
}

// ---------------------------------------------------------------------------
// Launch: 2-stage pipeline. Transposes (half-size, 2048 blocks each) on a
// forked stream; gather(half) waits on its transpose via event edges.
// Timeline: T0 -> [G0 || T1] -> G1.
// ---------------------------------------------------------------------------
extern "C" void kernel_launch(void* const* d_in, const int* in_sizes, int n_in,
                              void* d_out, int out_size) {
    const float* tk_codes = (const float*)d_in[0];   // [B, P, 2] float32
    const float* feat     = (const float*)d_in[1];   // [B, C, H, W] float32
    float* out            = (float*)d_out;           // [B, P, C] float32

    (void)in_sizes; (void)n_in; (void)out_size;

    static cudaStream_t s2 = nullptr;
    static cudaEvent_t evFork = nullptr, evT0 = nullptr, evT1 = nullptr;
    if (s2 == nullptr) {
        cudaStreamCreateWithFlags(&s2, cudaStreamNonBlocking);
        cudaEventCreateWithFlags(&evFork, cudaEventDisableTiming);
        cudaEventCreateWithFlags(&evT0, cudaEventDisableTiming);
        cudaEventCreateWithFlags(&evT1, cudaEventDisableTiming);
    }

    dim3 tgrid(HW / 128, CC / 32, HALFB);        // 2048 blocks per half
    dim3 tblock(32, 8);
    const int gblocks = (HALFB * PP / 8) * 32 / 256;  // 2048 blocks per half

    // fork s2 off the main (capture) stream
    cudaEventRecord(evFork, 0);
    cudaStreamWaitEvent(s2, evFork, 0);

    transpose_kernel<<<tgrid, tblock, 0, s2>>>(feat, 0);
    cudaEventRecord(evT0, s2);
    transpose_kernel<<<tgrid, tblock, 0, s2>>>(feat, HALFB);
    cudaEventRecord(evT1, s2);

    cudaStreamWaitEvent(0, evT0, 0);
    gather_kernel<<<gblocks, 256>>>(tk_codes, out, 0);
    cudaStreamWaitEvent(0, evT1, 0);
    gather_kernel<<<gblocks, 256>>>(tk_codes, out, HALFB);
}

// round 11
// speedup vs baseline: 1.3147x; 1.0443x over previous
#include <cuda_runtime.h>
#include <cuda_fp16.h>
#include <cstdint>

// Problem constants (fixed by the reference)
#define BB 8
#define CC 128
#define HH 128
#define WW 128
#define PP 32768
#define HW (HH * WW)

// Scratch: feat_grid transposed to [B, H*W, C] channels-last, fp16. 33.5 MB.
__device__ __half g_featT[BB * HW * CC];

// bit-cast helpers
static __device__ __forceinline__ unsigned h2_to_u32(__half2 h) {
    return *reinterpret_cast<unsigned*>(&h);
}
static __device__ __forceinline__ __half2 u32_to_h2(unsigned u) {
    return *reinterpret_cast<__half2*>(&u);
}

// ---------------------------------------------------------------------------
// Kernel 1: tiled transpose + f32->fp16:  src[C][HW] -> dstT[HW][C] (half)
// Tile: 32 channels x 128 hw. grid: (HW/128, CC/32, B), block: (32, 8).
// ---------------------------------------------------------------------------
__global__ void transpose_kernel(const float* __restrict__ src) {
    __shared__ float tile[32][129];

    const int b = blockIdx.z;
    const int hw0 = blockIdx.x * 128;
    const int c0 = blockIdx.y * 32;
    const float* sb = src + (size_t)b * CC * HW;
    __half2* db = (__half2*)(g_featT + (size_t)b * HW * CC);

    const int tx = threadIdx.x, ty = threadIdx.y;

    // read: each thread loads 4 float4 (rows c0+ty+8j, cols hw0+4tx..)
#pragma unroll
    for (int jj = 0; jj < 4; jj++) {
        const int c = ty + jj * 8;
        const float4 v = __ldcs((const float4*)&sb[(size_t)(c0 + c) * HW + hw0] + tx);
        tile[c][4 * tx + 0] = v.x;
        tile[c][4 * tx + 1] = v.y;
        tile[c][4 * tx + 2] = v.z;
        tile[c][4 * tx + 3] = v.w;
    }
    __syncthreads();

    // write: thread t -> h2 col (t&15), row group (t>>4); 8 passes of 16 rows
    const int t = ty * 32 + tx;
    const int col = t & 15;
    const int rowg = t >> 4;
#pragma unroll
    for (int pass = 0; pass < 8; pass++) {
        const int row = rowg + pass * 16;
        const float lo = tile[2 * col][row];
        const float hi = tile[2 * col + 1][row];
        db[(size_t)(hw0 + row) * (CC / 2) + (c0 >> 1) + col] =
            __floats2half2_rn(lo, hi);
    }
}

// ---------------------------------------------------------------------------
// Kernel 2: EIGHT points per warp, processed 2 at a time with batched loads
// (8 outstanding LDG.64 per dependency wave). HFMA2 accumulation.
// ---------------------------------------------------------------------------
__global__ __launch_bounds__(256) void gather_kernel(
    const float* __restrict__ tk_codes,   // [B, P, 2]
    float* __restrict__ out)              // [B, P, C]
{
    const unsigned FULL = 0xffffffffu;
    const int oct = (blockIdx.x * blockDim.x + threadIdx.x) >> 5;  // 8-point group
    const int lane = threadIdx.x & 31;

    const int p0 = oct * 8;                  // first point of this warp's group
    const int j = lane >> 2;                 // this lane's point (0..7)
    const int k = lane & 3;                  // this lane's corner

    const float2 pt = __ldg(((const float2*)tk_codes) + p0 + j);
    const float x = pt.x;
    const float y = pt.y;

    const bool inb = (x >= 0.0f) & (y >= 0.0f) &
                     (x <= (float)(WW - 1)) & (y <= (float)(HH - 1));

    // corner order: (fx,fy),(fx,cy),(cx,fy),(cx,cy)
    const float cxk = (k & 2) ? ceilf(x) : floorf(x);
    const float cyk = (k & 1) ? ceilf(y) : floorf(y);

    int gx = ((int)cxk) % WW;   // C-style %: matches jnp.fmod on int32
    int gy = ((int)cyk) % HH;
    gx = max(gx, 0);
    gy = max(gy, 0);

    const float dx = x - (float)gx;
    const float dy = y - (float)gy;
    float w = inb ? __fdividef(1.0f, sqrtf(dx * dx + dy * dy) + 1e-10f) : 0.0f;

    // butterfly within each 4-lane corner group
    float d = w + __shfl_xor_sync(FULL, w, 1);
    d += __shfl_xor_sync(FULL, d, 2);
    if (d == 0.0f) d = 1.0f;
    w *= __fdividef(1.0f, d);               // normalized weight in [0,1]

    const int idx = (gy << 7) + gx;
    const unsigned hw2 = h2_to_u32(__float2half2_rn(w));

    const int b = p0 >> 15;                  // P = 32768; group never spans batches
    const uint2* __restrict__ baseT =
        (const uint2*)(g_featT + (size_t)b * HW * CC);
    float4* __restrict__ o4 = (float4*)out;

    // process 2 points per step: 16 shfls -> 8 batched loads -> 2 acc chains
#pragma unroll
    for (int p = 0; p < 8; p += 2) {
        const int sA = p * 4, sB = (p + 1) * 4;

        const __half2 wA0 = u32_to_h2(__shfl_sync(FULL, hw2, sA + 0));
        const __half2 wA1 = u32_to_h2(__shfl_sync(FULL, hw2, sA + 1));
        const __half2 wA2 = u32_to_h2(__shfl_sync(FULL, hw2, sA + 2));
        const __half2 wA3 = u32_to_h2(__shfl_sync(FULL, hw2, sA + 3));
        const __half2 wB0 = u32_to_h2(__shfl_sync(FULL, hw2, sB + 0));
        const __half2 wB1 = u32_to_h2(__shfl_sync(FULL, hw2, sB + 1));
        const __half2 wB2 = u32_to_h2(__shfl_sync(FULL, hw2, sB + 2));
        const __half2 wB3 = u32_to_h2(__shfl_sync(FULL, hw2, sB + 3));
        const int iA0 = __shfl_sync(FULL, idx, sA + 0);
        const int iA1 = __shfl_sync(FULL, idx, sA + 1);
        const int iA2 = __shfl_sync(FULL, idx, sA + 2);
        const int iA3 = __shfl_sync(FULL, idx, sA + 3);
        const int iB0 = __shfl_sync(FULL, idx, sB + 0);
        const int iB1 = __shfl_sync(FULL, idx, sB + 1);
        const int iB2 = __shfl_sync(FULL, idx, sB + 2);
        const int iB3 = __shfl_sync(FULL, idx, sB + 3);

        // 8 independent corner-row loads in flight
        const uint2 rA0 = baseT[(size_t)iA0 * 32 + lane];
        const uint2 rA1 = baseT[(size_t)iA1 * 32 + lane];
        const uint2 rA2 = baseT[(size_t)iA2 * 32 + lane];
        const uint2 rA3 = baseT[(size_t)iA3 * 32 + lane];
        const uint2 rB0 = baseT[(size_t)iB0 * 32 + lane];
        const uint2 rB1 = baseT[(size_t)iB1 * 32 + lane];
        const uint2 rB2 = baseT[(size_t)iB2 * 32 + lane];
        const uint2 rB3 = baseT[(size_t)iB3 * 32 + lane];

        __half2 a0 = __hmul2(wA0, u32_to_h2(rA0.x));
        __half2 a1 = __hmul2(wA0, u32_to_h2(rA0.y));
        a0 = __hfma2(wA1, u32_to_h2(rA1.x), a0);
        a1 = __hfma2(wA1, u32_to_h2(rA1.y), a1);
        a0 = __hfma2(wA2, u32_to_h2(rA2.x), a0);
        a1 = __hfma2(wA2, u32_to_h2(rA2.y), a1);
        a0 = __hfma2(wA3, u32_to_h2(rA3.x), a0);
        a1 = __hfma2(wA3, u32_to_h2(rA3.y), a1);

        __half2 b0 = __hmul2(wB0, u32_to_h2(rB0.x));
        __half2 b1 = __hmul2(wB0, u32_to_h2(rB0.y));
        b0 = __hfma2(wB1, u32_to_h2(rB1.x), b0);
        b1 = __hfma2(wB1, u32_to_h2(rB1.y), b1);
        b0 = __hfma2(wB2, u32_to_h2(rB2.x), b0);
        b1 = __hfma2(wB2, u32_to_h2(rB2.y), b1);
        b0 = __hfma2(wB3, u32_to_h2(rB3.x), b0);
        b1 = __hfma2(wB3, u32_to_h2(rB3.y), b1);

        const float2 fA0 = __half22float2(a0);
        const float2 fA1 = __half22float2(a1);
        __stcs(o4 + (size_t)(p0 + p) * 32 + lane,
               make_float4(fA0.x, fA0.y, fA1.x, fA1.y));
        const float2 fB0 = __half22float2(b0);
        const float2 fB1 = __half22float2(b1);
        __stcs(o4 + (size_t)(p0 + p + 1) * 32 + lane,
               make_float4(fB0.x, fB0.y, fB1.x, fB1.y));
    }
}

// ---------------------------------------------------------------------------
extern "C" void kernel_launch(void* const* d_in, const int* in_sizes, int n_in,
                              void* d_out, int out_size) {
    const float* tk_codes = (const float*)d_in[0];   // [B, P, 2] float32
    const float* feat     = (const float*)d_in[1];   // [B, C, H, W] float32
    float* out            = (float*)d_out;           // [B, P, C] float32

    (void)in_sizes; (void)n_in; (void)out_size;

    dim3 tgrid(HW / 128, CC / 32, BB);
    dim3 tblock(32, 8);
    transpose_kernel<<<tgrid, tblock>>>(feat);

    const int total_octs = BB * PP / 8;          // 32768 groups, 1 warp each
    const int threads = 256;                     // 8 warps/block
    const int blocks = (total_octs * 32) / threads;
    gather_kernel<<<blocks, threads>>>(tk_codes, out);
}

// round 12
// speedup vs baseline: 1.3294x; 1.0112x over previous
#include <cuda_runtime.h>
#include <cuda_fp16.h>
#include <cstdint>

// Problem constants (fixed by the reference)
#define BB 8
#define CC 128
#define HH 128
#define WW 128
#define PP 32768
#define HW (HH * WW)

// Scratch: feat_grid transposed to [B, H*W, C] channels-last, fp16. 33.5 MB.
__device__ __half g_featT[BB * HW * CC];

// bit-cast helpers
static __device__ __forceinline__ __half2 u32_to_h2(unsigned u) {
    return *reinterpret_cast<__half2*>(&u);
}

// ---------------------------------------------------------------------------
// Kernel 1: tiled transpose + f32->fp16:  src[C][HW] -> dstT[HW][C] (half)
// Tile: 32 channels x 128 hw. grid: (HW/128, CC/32, B), block: (32, 8).
// ---------------------------------------------------------------------------
__global__ void transpose_kernel(const float* __restrict__ src) {
    __shared__ float tile[32][129];

    const int b = blockIdx.z;
    const int hw0 = blockIdx.x * 128;
    const int c0 = blockIdx.y * 32;
    const float* sb = src + (size_t)b * CC * HW;
    __half2* db = (__half2*)(g_featT + (size_t)b * HW * CC);

    const int tx = threadIdx.x, ty = threadIdx.y;

    // read: each thread loads 4 float4 (rows c0+ty+8j, cols hw0+4tx..)
#pragma unroll
    for (int jj = 0; jj < 4; jj++) {
        const int c = ty + jj * 8;
        const float4 v = __ldcs((const float4*)&sb[(size_t)(c0 + c) * HW + hw0] + tx);
        tile[c][4 * tx + 0] = v.x;
        tile[c][4 * tx + 1] = v.y;
        tile[c][4 * tx + 2] = v.z;
        tile[c][4 * tx + 3] = v.w;
    }
    __syncthreads();

    // write: thread t -> h2 col (t&15), row group (t>>4); 8 passes of 16 rows
    const int t = ty * 32 + tx;
    const int col = t & 15;
    const int rowg = t >> 4;
#pragma unroll
    for (int pass = 0; pass < 8; pass++) {
        const int row = rowg + pass * 16;
        const float lo = tile[2 * col][row];
        const float hi = tile[2 * col + 1][row];
        db[(size_t)(hw0 + row) * (CC / 2) + (c0 >> 1) + col] =
            __floats2half2_rn(lo, hi);
    }
}

// ---------------------------------------------------------------------------
// Kernel 2: EIGHT points per warp; (weight, index) packed into ONE u32 per
// corner -> 4 broadcast shfls per point instead of 8 (MIO pressure -30%).
// Unpack via PRMT (dup hi-half -> half2) + LOP3 (mask) on the idle ALU pipe.
// ---------------------------------------------------------------------------
__global__ __launch_bounds__(256) void gather_kernel(
    const float* __restrict__ tk_codes,   // [B, P, 2]
    float* __restrict__ out)              // [B, P, C]
{
    const unsigned FULL = 0xffffffffu;
    const int oct = (blockIdx.x * blockDim.x + threadIdx.x) >> 5;  // 8-point group
    const int lane = threadIdx.x & 31;

    const int p0 = oct * 8;                  // first point of this warp's group
    const int j = lane >> 2;                 // this lane's point (0..7)
    const int k = lane & 3;                  // this lane's corner

    const float2 pt = __ldg(((const float2*)tk_codes) + p0 + j);
    const float x = pt.x;
    const float y = pt.y;

    const bool inb = (x >= 0.0f) & (y >= 0.0f) &
                     (x <= (float)(WW - 1)) & (y <= (float)(HH - 1));

    // corner order: (fx,fy),(fx,cy),(cx,fy),(cx,cy)
    const float cxk = (k & 2) ? ceilf(x) : floorf(x);
    const float cyk = (k & 1) ? ceilf(y) : floorf(y);

    int gx = ((int)cxk) % WW;   // C-style %: matches jnp.fmod on int32
    int gy = ((int)cyk) % HH;
    gx = max(gx, 0);
    gy = max(gy, 0);

    const float dx = x - (float)gx;
    const float dy = y - (float)gy;
    float w = inb ? __fdividef(1.0f, sqrtf(dx * dx + dy * dy) + 1e-10f) : 0.0f;

    // butterfly within each 4-lane corner group
    float d = w + __shfl_xor_sync(FULL, w, 1);
    d += __shfl_xor_sync(FULL, d, 2);
    if (d == 0.0f) d = 1.0f;
    w *= __fdividef(1.0f, d);               // normalized weight in [0,1]

    const int idx = (gy << 7) + gx;          // 14 bits

    // pack: [31:16] = half(w), [13:0] = idx  (one shfl carries both)
    const unsigned wbits = (unsigned)__half_as_ushort(__float2half_rn(w));
    const unsigned packed = (wbits << 16) | (unsigned)idx;

    const int b = p0 >> 15;                  // P = 32768; group never spans batches
    const uint2* __restrict__ baseT =
        (const uint2*)(g_featT + (size_t)b * HW * CC);
    float4* __restrict__ o4 = (float4*)out;

#pragma unroll
    for (int p = 0; p < 8; p++) {
        const int s = p * 4;
        const unsigned v0 = __shfl_sync(FULL, packed, s + 0);
        const unsigned v1 = __shfl_sync(FULL, packed, s + 1);
        const unsigned v2 = __shfl_sync(FULL, packed, s + 2);
        const unsigned v3 = __shfl_sync(FULL, packed, s + 3);

        // unpack: PRMT duplicates hi 16 bits into both halves -> half2 weight
        const __half2 w0 = u32_to_h2(__byte_perm(v0, v0, 0x3232));
        const __half2 w1 = u32_to_h2(__byte_perm(v1, v1, 0x3232));
        const __half2 w2 = u32_to_h2(__byte_perm(v2, v2, 0x3232));
        const __half2 w3 = u32_to_h2(__byte_perm(v3, v3, 0x3232));
        const int i0 = (int)(v0 & 0x3FFFu);
        const int i1 = (int)(v1 & 0x3FFFu);
        const int i2 = (int)(v2 & 0x3FFFu);
        const int i3 = (int)(v3 & 0x3FFFu);

        const uint2 r0 = baseT[(size_t)i0 * 32 + lane];
        const uint2 r1 = baseT[(size_t)i1 * 32 + lane];
        const uint2 r2 = baseT[(size_t)i2 * 32 + lane];
        const uint2 r3 = baseT[(size_t)i3 * 32 + lane];

        __half2 a0 = __hmul2(w0, u32_to_h2(r0.x));
        __half2 a1 = __hmul2(w0, u32_to_h2(r0.y));
        a0 = __hfma2(w1, u32_to_h2(r1.x), a0);
        a1 = __hfma2(w1, u32_to_h2(r1.y), a1);
        a0 = __hfma2(w2, u32_to_h2(r2.x), a0);
        a1 = __hfma2(w2, u32_to_h2(r2.y), a1);
        a0 = __hfma2(w3, u32_to_h2(r3.x), a0);
        a1 = __hfma2(w3, u32_to_h2(r3.y), a1);

        const float2 f0 = __half22float2(a0);
        const float2 f1 = __half22float2(a1);
        __stcs(o4 + (size_t)(p0 + p) * 32 + lane,
               make_float4(f0.x, f0.y, f1.x, f1.y));
    }
}

// ---------------------------------------------------------------------------
extern "C" void kernel_launch(void* const* d_in, const int* in_sizes, int n_in,
                              void* d_out, int out_size) {
    const float* tk_codes = (const float*)d_in[0];   // [B, P, 2] float32
    const float* feat     = (const float*)d_in[1];   // [B, C, H, W] float32
    float* out            = (float*)d_out;           // [B, P, C] float32

    (void)in_sizes; (void)n_in; (void)out_size;

    dim3 tgrid(HW / 128, CC / 32, BB);
    dim3 tblock(32, 8);
    transpose_kernel<<<tgrid, tblock>>>(feat);

    const int total_octs = BB * PP / 8;          // 32768 groups, 1 warp each
    const int threads = 256;                     // 8 warps/block
    const int blocks = (total_octs * 32) / threads;
    gather_kernel<<<blocks, threads>>>(tk_codes, out);
}